// round 7
// baseline (speedup 1.0000x reference)
#include <cuda_runtime.h>

#define WH    128
#define NPIX  (WH*WH)      // 16384
#define NB    2
#define NBLK  64           // persistent grid, 32 blocks per batch
#define TPB   512          // 4 rows per block
#define BAND  20           // staged mask rows: 4 own + 8 up + 8 down

// Scratch (no allocations allowed)
__device__ float    g_smax[NBLK * 16];   // per-block per-label max(d); no atomics
__device__ float    g_part[NBLK];        // per-block loss partials
__device__ unsigned g_cnt[64];           // [0]=batch0 barrier, [32]=batch1 (cacheline-split)
__device__ unsigned g_done = 0;          // monotonic arrival counter (final reduce)

// Per-batch barrier: monotonic ticket counter, replay-safe, 32 arrivals.
__device__ __forceinline__ void batchbar(int b)
{
    __threadfence();
    __syncthreads();
    if (threadIdx.x == 0) {
        unsigned* c = &g_cnt[b * 32];
        unsigned ticket = atomicAdd(c, 1u) + 1u;
        unsigned target = ((ticket + 31u) / 32u) * 32u;
        volatile unsigned* vc = c;
        while (*vc < target) { }
    }
    __syncthreads();
    __threadfence();
}

__global__ __launch_bounds__(TPB, 1) void fused_kernel(
    const float* __restrict__ pred,
    const int*   __restrict__ mask,
    const float* __restrict__ ign,
    float* __restrict__ out)
{
    const int tid = threadIdx.x;
    const int bx  = blockIdx.x;

    const int p  = bx * TPB + tid;        // pixel id 0..32767 (row-major)
    const int b  = p >> 14;               // batch (32 blocks per batch)
    const int xy = p & (NPIX - 1);
    const int i0 = xy >> 7;               // this pixel's row
    const int j  = xy & 127;
    const int r0 = tid >> 7;              // 0..3: which of the block's 4 rows
    const int base_i  = (bx & 31) * 4;
    const int band_lo = max(0, base_i - 8);
    const int band_hi = min(WH, base_i + 4 + 8);

    __shared__ unsigned char s_band[BAND * WH];   // 2.5KB mask band (bytes)
    __shared__ float    s_rm2[4][WH];
    __shared__ unsigned smax[16];
    __shared__ float    s_gm[16];
    __shared__ float    ws[16];
    __shared__ int      s_last;

    // ---- Early prefetch (independent; hides DRAM/L2 latency) ----------------
    const float* pp = pred + b * 8 * NPIX + xy;
    float pr[8];
    #pragma unroll
    for (int c = 0; c < 8; c++) pr[c] = pp[c * NPIX];
    const float w_ign = ign[p];

    // ---- Load the mask band into shared as bytes (int4 + 3x prmt) -----------
    {
        const int nwords = (band_hi - band_lo) * (WH / 4);      // <= 640 int4
        const int4* m4 = (const int4*)(mask + b * NPIX + band_lo * WH);
        unsigned* sm32 = (unsigned*)s_band;
        #pragma unroll
        for (int k = 0; k < 2; k++) {
            int idx = tid + k * TPB;
            if (idx < nwords) {
                int4 v = m4[idx];
                unsigned t1 = __byte_perm((unsigned)v.x, (unsigned)v.y, 0x0040);
                unsigned t2 = __byte_perm((unsigned)v.z, (unsigned)v.w, 0x0040);
                sm32[idx] = __byte_perm(t1, t2, 0x5410);
            }
        }
    }
    if (tid < 16) smax[tid] = 0u;
    __syncthreads();

    const unsigned char* bj = s_band - band_lo * WH + j;   // band col j, global row idx
    const int lab = bj[i0 * WH];

    // ---- rm2 at own pixel: vertical same-label run distance^2 ---------------
    // Batched: 16 independent LDS (8 up, 8 down) -> bitmask -> ffs. Fallback
    // (runs >= 8, P ~ 17^-8) walks GLOBAL mask — exact.
    {
        const int* gcol = mask + b * NPIX + j;
        unsigned upb = 0, dnb = 0;
        #pragma unroll
        for (int t = 1; t <= 8; t++) {
            int iu = i0 - t, idn = i0 + t;
            if (iu >= 0  && bj[iu  * WH] == lab) upb |= 1u << (t - 1);
            if (idn < WH && bj[idn * WH] == lab) dnb |= 1u << (t - 1);
        }
        int ru = __ffs(~upb) - 1;
        if (ru == 8) { while (i0 - 1 - ru >= 0 && gcol[(i0 - 1 - ru) * WH] == lab) ru++; }
        const int du = (i0 - 1 - ru >= 0) ? ru + 1 : 1000;

        int rd = __ffs(~dnb) - 1;
        if (rd == 8) { while (i0 + 1 + rd < WH && gcol[(i0 + 1 + rd) * WH] == lab) rd++; }
        const int dd = (i0 + 1 + rd < WH) ? rd + 1 : 1000;

        const int md = min(du, dd);
        s_rm2[r0][j] = (md >= WH) ? 1e9f : (float)(md * md);
    }
    __syncthreads();

    // ---- Adaptive row envelope (bit-exact early cutoff) ---------------------
    // d^2 = min_{j'} v[j'] + (j-j')^2, v[j'] = (lab'==lab ? rm2[j'] : 0) >= 0.
    float d = 0.f;
    {
        const unsigned char* mrow = s_band + (i0 - band_lo) * WH;
        float m = (lab > 0) ? s_rm2[r0][j] : 0.f;          // o = 0 term
        for (int o = 1; o < WH; o += 2) {
            float o2a = (float)(o * o);                    // exact integer
            if (__all_sync(0xFFFFFFFFu, o2a >= m)) break;
            int jl = j - o, jr = j + o;
            if (jl >= 0) { float v = (mrow[jl] == lab) ? s_rm2[r0][jl] : 0.f; m = fminf(m, o2a + v); }
            if (jr < WH) { float v = (mrow[jr] == lab) ? s_rm2[r0][jr] : 0.f; m = fminf(m, o2a + v); }
            int o1 = o + 1; float o2b = (float)(o1 * o1);
            int jl1 = j - o1, jr1 = j + o1;
            if (jl1 >= 0) { float v = (mrow[jl1] == lab) ? s_rm2[r0][jl1] : 0.f; m = fminf(m, o2b + v); }
            if (jr1 < WH) { float v = (mrow[jr1] == lab) ? s_rm2[r0][jr1] : 0.f; m = fminf(m, o2b + v); }
        }
        if (lab > 0) {
            d = __fsqrt_rn(m);                              // IEEE sqrt
            atomicMax(&smax[lab - 1], __float_as_uint(d));  // shared only; d>=0
        }
    }
    __syncthreads();
    // Publish block maxima: private slot, plain stores (no global atomics).
    if (tid < 16) __stcg(&g_smax[bx * 16 + tid], __uint_as_float(smax[tid]));

    // ---- Pre-barrier: both smooth-L1 candidates per channel (g=0 / g=1) ----
    float l1a[8], l1b[8];
    #pragma unroll
    for (int c = 0; c < 8; c++) {
        float da = pr[c];
        float aa = fabsf(da);
        l1a[c] = (aa < 1.f) ? 0.5f * da * da : (aa - 0.5f);
        float db = pr[c] - 1.f;
        float ab = fabsf(db);
        l1b[c] = (ab < 1.f) ? 0.5f * db * db : (ab - 0.5f);
    }

    batchbar(b);   // only this batch's 32 blocks

    // ---- Final per-label maxima: parallel fmax over the batch's 32 slots ----
    if (tid < 16) {
        const float* gs = g_smax + (b * 32) * 16 + tid;
        float mv = 0.f;
        #pragma unroll
        for (int s = 0; s < 32; s++) mv = fmaxf(mv, __ldcg(gs + s * 16));
        s_gm[tid] = mv;
    }
    __syncthreads();

    // ---- Bin select + gt write + loss --------------------------------------
    int c0 = -1;
    if (lab > 0) {
        float mv = s_gm[lab - 1];
        float dn = (mv > 0.f) ? __fdiv_rn(d, mv) : d;      // IEEE div
        if (dn < 0.5f) dn = 0.0f;
        if (dn > 0.7f) dn = 1.0f;
        const float DDD[8] = {0.83f, 0.68f, 0.54f, 0.41f, 0.29f, 0.18f, 0.09f, 0.0f};
        c0 = 7;
        #pragma unroll
        for (int c = 0; c < 8; c++)
            if (dn >= DDD[c]) { c0 = c; break; }
    }

    float* go = out + 1 + b * 8 * NPIX + xy;               // out[0] = loss
    float s = 0.f;
    #pragma unroll
    for (int c = 0; c < 8; c++) {
        bool hit = (c == c0);
        go[c * NPIX] = hit ? 1.f : 0.f;
        s += hit ? l1b[c] : l1a[c];                        // same terms, same order
    }
    float contrib = w_ign * s * 0.125f;                    // mean over C=8

    #pragma unroll
    for (int off = 16; off; off >>= 1)
        contrib += __shfl_xor_sync(0xFFFFFFFFu, contrib, off);
    if ((tid & 31) == 0) ws[tid >> 5] = contrib;
    __syncthreads();
    if (tid == 0) {
        float tsum = 0.f;
        #pragma unroll
        for (int u = 0; u < 16; u++) tsum += ws[u];
        g_part[bx] = tsum;
        __threadfence();
        unsigned t = atomicAdd(&g_done, 1u);
        s_last = (((t + 1u) & (NBLK - 1u)) == 0u);         // last arrival this replay
    }
    __syncthreads();

    // ---- Last block: deterministic final reduction --------------------------
    if (s_last) {
        __threadfence();
        float v = 0.f;
        if (tid < NBLK) {
            v = __ldcg(&g_part[tid]);
            #pragma unroll
            for (int off = 16; off; off >>= 1)
                v += __shfl_xor_sync(0xFFFFFFFFu, v, off);
            if ((tid & 31) == 0) ws[tid >> 5] = v;
        }
        __syncthreads();
        if (tid == 0)
            out[0] = (ws[0] + ws[1]) * (1.f / (float)(NB * NPIX));
    }
}

extern "C" void kernel_launch(void* const* d_in, const int* in_sizes, int n_in,
                              void* d_out, int out_size)
{
    const float* pred = (const float*)d_in[0];   // [2,8,128,128] f32
    const int*   mask = (const int*)  d_in[1];   // [2,128,128]   i32
    const float* ign  = (const float*)d_in[2];   // [2,128,128]   f32
    float* out = (float*)d_out;                  // [0]=loss, [1..]=gt

    fused_kernel<<<NBLK, TPB>>>(pred, mask, ign, out);
}

// round 8
// speedup vs baseline: 1.0239x; 1.0239x over previous
#include <cuda_runtime.h>

#define WH    128
#define NPIX  (WH*WH)      // 16384
#define NB    2
#define NBK   32           // 2 batches x 16 instances
#define NBLK  128          // persistent grid, 64 blocks per batch
#define TPB   256          // 2 rows per block

// Scratch (no allocations allowed)
__device__ unsigned g_max[NBK];          // per-(b,k) max(d) as ordered uint (reset by last block)
__device__ float    g_part[NBLK];        // per-block loss partials
__device__ unsigned g_cnt[64];           // [0]=batch0 barrier, [32]=batch1 (separate lines)
__device__ unsigned g_done = 0;          // monotonic arrival counter (final reduce)

// Per-batch barrier: monotonic ticket counter, replay-safe, 64 arrivals.
__device__ __forceinline__ void batchbar(int b)
{
    __threadfence();
    __syncthreads();
    if (threadIdx.x == 0) {
        unsigned* c = &g_cnt[b * 32];
        unsigned ticket = atomicAdd(c, 1u) + 1u;
        unsigned target = ((ticket + 63u) / 64u) * 64u;
        volatile unsigned* vc = c;
        while (*vc < target) { }
    }
    __syncthreads();
    __threadfence();
}

__global__ __launch_bounds__(TPB, 1) void fused_kernel(
    const float* __restrict__ pred,
    const int*   __restrict__ mask,
    const float* __restrict__ ign,
    float* __restrict__ out)
{
    const int tid = threadIdx.x;
    const int bx  = blockIdx.x;

    const int p  = bx * TPB + tid;        // pixel id 0..32767 (row-major)
    const int b  = p >> 14;               // batch (64 blocks per batch)
    const int xy = p & (NPIX - 1);
    const int i0 = xy >> 7;               // this pixel's row
    const int j  = xy & 127;
    const int r0 = tid >> 7;              // 0/1: which of the block's 2 rows

    __shared__ unsigned char s_lab[2][WH];
    __shared__ float    s_rm2[2][WH];
    __shared__ unsigned smax[16];
    __shared__ float    s_gm[16];
    __shared__ float    ws[8];
    __shared__ int      s_last;

    // ---- Early prefetch (independent; hides DRAM/L2 latency) ----------------
    const float* pp = pred + b * 8 * NPIX + xy;
    float pr[8];
    #pragma unroll
    for (int c = 0; c < 8; c++) pr[c] = pp[c * NPIX];
    const float w_ign = ign[p];

    if (tid < 16) smax[tid] = 0u;

    // ---- Own label + vertical ±8 neighbors straight from global -------------
    // For fixed neighbor row, lanes have consecutive j -> 128B coalesced LDG.
    // All 17 loads independent: one L2 latency window.
    const int* gpix = mask + b * NPIX + i0 * WH + j;
    const int lab = *gpix;
    s_lab[r0][j] = (unsigned char)lab;

    {
        unsigned upb = 0, dnb = 0;
        #pragma unroll
        for (int t = 1; t <= 8; t++) {
            if (i0 - t >= 0 && __ldg(gpix - t * WH) == lab) upb |= 1u << (t - 1);
            if (i0 + t < WH && __ldg(gpix + t * WH) == lab) dnb |= 1u << (t - 1);
        }
        int ru = __ffs(~upb) - 1;       // consecutive same-label run upward
        if (ru == 8) { while (i0 - 1 - ru >= 0 && gpix[-(1 + ru) * WH] == lab) ru++; }
        const int du = (i0 - 1 - ru >= 0) ? ru + 1 : 1000;

        int rd = __ffs(~dnb) - 1;       // downward
        if (rd == 8) { while (i0 + 1 + rd < WH && gpix[(1 + rd) * WH] == lab) rd++; }
        const int dd = (i0 + 1 + rd < WH) ? rd + 1 : 1000;

        const int md = min(du, dd);
        s_rm2[r0][j] = (md >= WH) ? 1e9f : (float)(md * md);
    }
    __syncthreads();

    // ---- Adaptive row envelope (bit-exact early cutoff) ---------------------
    // d^2 = min_{j'} v[j'] + (j-j')^2, v[j'] = (lab'==lab ? rm2[j'] : 0) >= 0.
    // Break when o^2 >= m for all lanes at the smaller o of each pair
    // (conservative; fminf over identical candidate set -> bit-identical).
    float d = 0.f;
    {
        const unsigned char* mrow = s_lab[r0];
        const float*         vrow = s_rm2[r0];
        const unsigned char lb = (unsigned char)lab;
        float m = (lab > 0) ? vrow[j] : 0.f;               // o = 0 term
        for (int o = 1; o < WH; o += 2) {
            float o2a = (float)(o * o);                    // exact integer
            if (__all_sync(0xFFFFFFFFu, o2a >= m)) break;
            int jl = j - o, jr = j + o;
            if (jl >= 0) { float v = (mrow[jl] == lb) ? vrow[jl] : 0.f; m = fminf(m, o2a + v); }
            if (jr < WH) { float v = (mrow[jr] == lb) ? vrow[jr] : 0.f; m = fminf(m, o2a + v); }
            int o1 = o + 1; float o2b = (float)(o1 * o1);
            int jl1 = j - o1, jr1 = j + o1;
            if (jl1 >= 0) { float v = (mrow[jl1] == lb) ? vrow[jl1] : 0.f; m = fminf(m, o2b + v); }
            if (jr1 < WH) { float v = (mrow[jr1] == lb) ? vrow[jr1] : 0.f; m = fminf(m, o2b + v); }
        }
        if (lab > 0) {
            d = __fsqrt_rn(m);                              // IEEE sqrt
            atomicMax(&smax[lab - 1], __float_as_uint(d));  // shared; d>=0
        }
    }
    __syncthreads();
    if (tid < 16 && smax[tid]) atomicMax(&g_max[(b << 4) + tid], smax[tid]);  // REDG, fire-and-forget

    // ---- Pre-barrier: gt zeros (drain during barrier) + both L1 candidates --
    float* go = out + 1 + b * 8 * NPIX + xy;               // out[0] = loss
    #pragma unroll
    for (int c = 0; c < 8; c++) go[c * NPIX] = 0.f;

    float l1a[8], l1b[8];
    #pragma unroll
    for (int c = 0; c < 8; c++) {
        float da = pr[c];
        float aa = fabsf(da);
        l1a[c] = (aa < 1.f) ? 0.5f * da * da : (aa - 0.5f);
        float db = pr[c] - 1.f;
        float ab = fabsf(db);
        l1b[c] = (ab < 1.f) ? 0.5f * db * db : (ab - 0.5f);
    }

    batchbar(b);   // only this batch's 64 blocks

    // ---- Final maxima for this batch (single L2 window) ---------------------
    if (tid < 16) s_gm[tid] = __uint_as_float(__ldcg(&g_max[(b << 4) + tid]));
    __syncthreads();

    // ---- Bin select + single hit store + loss (bit-exact term order) --------
    int c0 = -1;
    if (lab > 0) {
        float mv = s_gm[lab - 1];
        float dn = (mv > 0.f) ? __fdiv_rn(d, mv) : d;      // IEEE div
        if (dn < 0.5f) dn = 0.0f;
        if (dn > 0.7f) dn = 1.0f;
        const float DDD[8] = {0.83f, 0.68f, 0.54f, 0.41f, 0.29f, 0.18f, 0.09f, 0.0f};
        c0 = 7;
        #pragma unroll
        for (int c = 0; c < 8; c++)
            if (dn >= DDD[c]) { c0 = c; break; }
        go[c0 * NPIX] = 1.f;         // same thread, same address: ordered after 0
    }

    float s = 0.f;
    #pragma unroll
    for (int c = 0; c < 8; c++)
        s += (c == c0) ? l1b[c] : l1a[c];                  // same terms, same order
    float contrib = w_ign * s * 0.125f;                    // mean over C=8

    #pragma unroll
    for (int off = 16; off; off >>= 1)
        contrib += __shfl_xor_sync(0xFFFFFFFFu, contrib, off);
    if ((tid & 31) == 0) ws[tid >> 5] = contrib;
    __syncthreads();
    if (tid == 0) {
        float tsum = 0.f;
        #pragma unroll
        for (int u = 0; u < 8; u++) tsum += ws[u];
        g_part[bx] = tsum;
        __threadfence();
        unsigned t = atomicAdd(&g_done, 1u);
        s_last = (((t + 1u) & (NBLK - 1u)) == 0u);         // last arrival this replay
    }
    __syncthreads();

    // ---- Last block: reset maxima for next replay + deterministic reduction -
    if (s_last) {
        __threadfence();
        if (tid < NBK) g_max[tid] = 0u;
        float v = 0.f;
        if (tid < NBLK) {
            v = __ldcg(&g_part[tid]);
            #pragma unroll
            for (int off = 16; off; off >>= 1)
                v += __shfl_xor_sync(0xFFFFFFFFu, v, off);
            if ((tid & 31) == 0) ws[tid >> 5] = v;
        }
        __syncthreads();
        if (tid == 0)
            out[0] = ((ws[0] + ws[1]) + (ws[2] + ws[3])) * (1.f / (float)(NB * NPIX));
    }
}

extern "C" void kernel_launch(void* const* d_in, const int* in_sizes, int n_in,
                              void* d_out, int out_size)
{
    const float* pred = (const float*)d_in[0];   // [2,8,128,128] f32
    const int*   mask = (const int*)  d_in[1];   // [2,128,128]   i32
    const float* ign  = (const float*)d_in[2];   // [2,128,128]   f32
    float* out = (float*)d_out;                  // [0]=loss, [1..]=gt

    fused_kernel<<<NBLK, TPB>>>(pred, mask, ign, out);
}